// round 4
// baseline (speedup 1.0000x reference)
#include <cuda_runtime.h>
#include <cuda_bf16.h>
#include <cstdint>

#define BATCH  4096
#define NREL   128
#define EMB    256
#define KDIM   512
#define NCHUNK 16     // K' = 1024 in chunks of 64
#define MT     32     // M tile per CTA -> 128 CTAs
#define NS     5      // pipeline stages

// ---------------- device globals ----------------
// B chunk-major: [chunk][relation][64 bf16]  (16 KB per chunk, contiguous)
__device__ __align__(16) __nv_bfloat16 g_B2[NCHUNK * NREL * 64];
__device__ __align__(16) float g_const[NREL];

// ---------------- helpers ----------------
__device__ __forceinline__ uint32_t smem_u32(const void* p) {
    uint32_t a;
    asm("{ .reg .u64 t; cvta.to.shared.u64 t, %1; cvt.u32.u64 %0, t; }" : "=r"(a) : "l"(p));
    return a;
}
__device__ __forceinline__ void ldsm_x4(uint32_t& r0, uint32_t& r1, uint32_t& r2, uint32_t& r3,
                                        uint32_t addr) {
    asm volatile("ldmatrix.sync.aligned.m8n8.x4.shared.b16 {%0,%1,%2,%3}, [%4];"
                 : "=r"(r0), "=r"(r1), "=r"(r2), "=r"(r3) : "r"(addr));
}
__device__ __forceinline__ void mma16816(float* d, const uint32_t* a, uint32_t b0, uint32_t b1) {
    asm volatile(
        "mma.sync.aligned.m16n8k16.row.col.f32.bf16.bf16.f32 "
        "{%0,%1,%2,%3}, {%4,%5,%6,%7}, {%8,%9}, {%0,%1,%2,%3};"
        : "+f"(d[0]), "+f"(d[1]), "+f"(d[2]), "+f"(d[3])
        : "r"(a[0]), "r"(a[1]), "r"(a[2]), "r"(a[3]), "r"(b0), "r"(b1));
}
#define CP_ASYNC16(dst, src) \
    asm volatile("cp.async.cg.shared.global [%0], [%1], 16;" :: "r"(dst), "l"(src) : "memory")
#define CP_COMMIT() asm volatile("cp.async.commit_group;" ::: "memory")
#define CP_WAIT3()  asm volatile("cp.async.wait_group 3;" ::: "memory")

// ---------------- prep ----------------
__global__ void prep_kernel(const float* __restrict__ mus,
                            const float* __restrict__ sigmas,
                            const float* __restrict__ priors) {
    const int r = blockIdx.x;
    const int k = threadIdx.x;   // 0..511

    const float s    = sigmas[r * KDIM + k];
    const float mu   = mus[r * KDIM + k];
    const float inv2 = 1.0f / (s * s);

    const int c  = k >> 6;
    const int kk = k & 63;
    g_B2[(size_t)c * (NREL * 64) + r * 64 + kk]       = __float2bfloat16(-0.5f * inv2); // w2 <-> x^2
    g_B2[(size_t)(c + 8) * (NREL * 64) + r * 64 + kk] = __float2bfloat16(mu * inv2);    // w1 <-> x

    float part = -0.5f * mu * mu * inv2 - logf(s) - 0.9189385332046727f;

    __shared__ float red[16];
    #pragma unroll
    for (int off = 16; off > 0; off >>= 1)
        part += __shfl_down_sync(0xffffffffu, part, off);
    if ((k & 31) == 0) red[k >> 5] = part;
    __syncthreads();
    if (k < 16) {
        float v = red[k];
        #pragma unroll
        for (int off = 8; off > 0; off >>= 1)
            v += __shfl_down_sync(0x0000ffffu, v, off);
        if (k == 0) g_const[r] = v + priors[r] * (float)KDIM;
    }
}

// ---------------- main: 5-stage cp.async bf16 HMMA GEMM ----------------
// smem: A stages [NS][32*128B] then B stages [NS][128*128B]
#define SMA_OFF(s) ((s) * 4096)
#define SMB_OFF(s) (NS * 4096 + (s) * 16384)
#define SMEM_TOTAL (NS * 4096 + NS * 16384)   // 102400

__global__ __launch_bounds__(256)
void nb_mma(const float* __restrict__ sbjs,
            const float* __restrict__ objs,
            float* __restrict__ out) {
    extern __shared__ char smem[];
    const uint32_t sb = smem_u32(smem);

    const int tid  = threadIdx.x;
    const int lane = tid & 31;
    const int wid  = tid >> 5;
    const int brow = blockIdx.x * MT;

    // ---- loader mappings ----
    const int arow = tid >> 3;              // 0..31
    const int aoct = tid & 7;               // k-offset = aoct*8 floats
    const uint32_t aStsOff = (uint32_t)(arow * 128 + ((aoct * 16) ^ ((arow & 7) << 4)));

    const int brw  = tid >> 1;              // relation row 0..127
    const int bhlf = tid & 1;
    uint32_t bStsOff[4];
    #pragma unroll
    for (int j = 0; j < 4; j++)
        bStsOff[j] = (uint32_t)(brw * 128 + ((bhlf * 64 + j * 16) ^ ((brw & 7) << 4)));

    // ---- compute mappings ----
    const int wm = wid >> 2;                // m offset 16
    const int wn = wid & 3;                 // n offset 32
    const int mrow = wm * 16 + (lane & 15);
    const uint32_t aLdRow = (uint32_t)(mrow * 128);
    const uint32_t aLdXor = (uint32_t)((mrow & 7) << 4);
    const uint32_t aLdBlk = (uint32_t)((lane >> 4) * 16);

    const int nrow0 = wn * 32 + ((lane >> 4) * 8) + (lane & 7);
    const int nrow1 = nrow0 + 16;
    const uint32_t bLdBlk  = (uint32_t)(((lane >> 3) & 1) * 16);
    const uint32_t bLdRow0 = (uint32_t)(nrow0 * 128), bLdXor0 = (uint32_t)((nrow0 & 7) << 4);
    const uint32_t bLdRow1 = (uint32_t)(nrow1 * 128), bLdXor1 = (uint32_t)((nrow1 & 7) << 4);

    float acc[4][4];
    #pragma unroll
    for (int i = 0; i < 4; i++)
        #pragma unroll
        for (int j = 0; j < 4; j++) acc[i][j] = 0.0f;

    // helpers
    auto ldgA = [&](int c, float4& v0, float4& v1) {
        const int ck = c & 7;
        const int k  = ck * 64 + aoct * 8;
        const float* src = (k < EMB)
            ? sbjs + (size_t)(brow + arow) * EMB + k
            : objs + (size_t)(brow + arow) * EMB + (k - EMB);
        v0 = reinterpret_cast<const float4*>(src)[0];
        v1 = reinterpret_cast<const float4*>(src)[1];
    };
    auto stsA = [&](int c, float4 v0, float4 v1) {
        if (c < 8) {
            v0.x *= v0.x; v0.y *= v0.y; v0.z *= v0.z; v0.w *= v0.w;
            v1.x *= v1.x; v1.y *= v1.y; v1.z *= v1.z; v1.w *= v1.w;
        }
        __nv_bfloat162 h0 = __floats2bfloat162_rn(v0.x, v0.y);
        __nv_bfloat162 h1 = __floats2bfloat162_rn(v0.z, v0.w);
        __nv_bfloat162 h2 = __floats2bfloat162_rn(v1.x, v1.y);
        __nv_bfloat162 h3 = __floats2bfloat162_rn(v1.z, v1.w);
        uint4 u;
        u.x = *reinterpret_cast<uint32_t*>(&h0);
        u.y = *reinterpret_cast<uint32_t*>(&h1);
        u.z = *reinterpret_cast<uint32_t*>(&h2);
        u.w = *reinterpret_cast<uint32_t*>(&h3);
        *reinterpret_cast<uint4*>(smem + SMA_OFF(c % NS) + aStsOff) = u;
    };
    auto issueB = [&](int c) {
        const char* src = reinterpret_cast<const char*>(g_B2) + (size_t)c * 16384 + tid * 64;
        const uint32_t dst = sb + SMB_OFF(c % NS);
        #pragma unroll
        for (int j = 0; j < 4; j++)
            CP_ASYNC16(dst + bStsOff[j], src + j * 16);
    };

    // ---- prologue: chunks 0..3 ----
    #pragma unroll
    for (int p = 0; p < NS - 1; p++) { issueB(p); CP_COMMIT(); }
    {
        float4 a0[NS - 1], a1[NS - 1];
        #pragma unroll
        for (int p = 0; p < NS - 1; p++) ldgA(p, a0[p], a1[p]);
        #pragma unroll
        for (int p = 0; p < NS - 1; p++) stsA(p, a0[p], a1[p]);
    }

    // ---- main loop ----
    for (int c = 0; c < NCHUNK; c++) {
        const int s = c % NS;
        CP_WAIT3();
        __syncthreads();

        // prefetch chunk c+4
        float4 pv0, pv1;
        const bool have_next = (c + NS - 1 < NCHUNK);
        if (have_next) {
            ldgA(c + NS - 1, pv0, pv1);
            issueB(c + NS - 1);
        }
        CP_COMMIT();   // unconditional: keeps wait_group count aligned

        // compute chunk c
        const uint32_t aB = sb + SMA_OFF(s);
        const uint32_t bB = sb + SMB_OFF(s);
        #pragma unroll
        for (int ks = 0; ks < 4; ks++) {
            const uint32_t kcol = (uint32_t)(ks * 32);
            uint32_t a[4];
            ldsm_x4(a[0], a[1], a[2], a[3], aB + aLdRow + ((kcol + aLdBlk) ^ aLdXor));
            uint32_t b[8];
            ldsm_x4(b[0], b[1], b[2], b[3], bB + bLdRow0 + ((kcol + bLdBlk) ^ bLdXor0));
            ldsm_x4(b[4], b[5], b[6], b[7], bB + bLdRow1 + ((kcol + bLdBlk) ^ bLdXor1));
            #pragma unroll
            for (int nf = 0; nf < 4; nf++)
                mma16816(acc[nf], a, b[nf * 2], b[nf * 2 + 1]);
        }

        if (have_next) stsA(c + NS - 1, pv0, pv1);
    }

    // ---- epilogue: accum + const -> global ----
    #pragma unroll
    for (int nf = 0; nf < 4; nf++) {
        const int n0 = wn * 32 + nf * 8 + (lane & 3) * 2;
        const float c0 = g_const[n0], c1 = g_const[n0 + 1];
        const int r0 = brow + wm * 16 + (lane >> 2);
        float2 o0, o1;
        o0.x = acc[nf][0] + c0; o0.y = acc[nf][1] + c1;
        o1.x = acc[nf][2] + c0; o1.y = acc[nf][3] + c1;
        *reinterpret_cast<float2*>(&out[(size_t)r0 * NREL + n0])       = o0;
        *reinterpret_cast<float2*>(&out[(size_t)(r0 + 8) * NREL + n0]) = o1;
    }
}

extern "C" void kernel_launch(void* const* d_in, const int* in_sizes, int n_in,
                              void* d_out, int out_size) {
    const float* sbjs   = (const float*)d_in[0];
    const float* objs   = (const float*)d_in[1];
    const float* mus    = (const float*)d_in[2];
    const float* sigmas = (const float*)d_in[3];
    const float* priors = (const float*)d_in[4];
    float* out = (float*)d_out;

    cudaFuncSetAttribute(nb_mma, cudaFuncAttributeMaxDynamicSharedMemorySize, SMEM_TOTAL);

    prep_kernel<<<NREL, KDIM>>>(mus, sigmas, priors);
    nb_mma<<<BATCH / MT, 256, SMEM_TOTAL>>>(sbjs, objs, out);
    (void)in_sizes; (void)n_in; (void)out_size;
}

// round 5
// speedup vs baseline: 1.2561x; 1.2561x over previous
#include <cuda_runtime.h>
#include <cuda_bf16.h>
#include <cstdint>

#define BATCH  4096
#define NREL   128
#define EMB    256
#define KDIM   512
#define NCHUNK 16     // K' = 1024 in chunks of 64
#define MT     32     // M tile per CTA -> 128 CTAs
#define NS     4      // B pipeline stages

// ---------------- device globals ----------------
// B chunk-major: [chunk][relation][64 bf16]  (16 KB per chunk, contiguous)
__device__ __align__(16) __nv_bfloat16 g_B2[NCHUNK * NREL * 64];
__device__ __align__(16) float g_const[NREL];

// ---------------- helpers ----------------
__device__ __forceinline__ uint32_t smem_u32(const void* p) {
    uint32_t a;
    asm("{ .reg .u64 t; cvta.to.shared.u64 t, %1; cvt.u32.u64 %0, t; }" : "=r"(a) : "l"(p));
    return a;
}
__device__ __forceinline__ void ldsm_x4(uint32_t& r0, uint32_t& r1, uint32_t& r2, uint32_t& r3,
                                        uint32_t addr) {
    asm volatile("ldmatrix.sync.aligned.m8n8.x4.shared.b16 {%0,%1,%2,%3}, [%4];"
                 : "=r"(r0), "=r"(r1), "=r"(r2), "=r"(r3) : "r"(addr));
}
__device__ __forceinline__ void mma16816(float* d, const uint32_t* a, uint32_t b0, uint32_t b1) {
    asm volatile(
        "mma.sync.aligned.m16n8k16.row.col.f32.bf16.bf16.f32 "
        "{%0,%1,%2,%3}, {%4,%5,%6,%7}, {%8,%9}, {%0,%1,%2,%3};"
        : "+f"(d[0]), "+f"(d[1]), "+f"(d[2]), "+f"(d[3])
        : "r"(a[0]), "r"(a[1]), "r"(a[2]), "r"(a[3]), "r"(b0), "r"(b1));
}
#define CP_ASYNC16(dst, src) \
    asm volatile("cp.async.cg.shared.global [%0], [%1], 16;" :: "r"(dst), "l"(src) : "memory")
#define CP_COMMIT() asm volatile("cp.async.commit_group;" ::: "memory")
#define CP_WAIT2()  asm volatile("cp.async.wait_group 2;" ::: "memory")

// ---------------- prep ----------------
__global__ void prep_kernel(const float* __restrict__ mus,
                            const float* __restrict__ sigmas,
                            const float* __restrict__ priors) {
    const int r = blockIdx.x;
    const int k = threadIdx.x;   // 0..511

    const float s    = sigmas[r * KDIM + k];
    const float mu   = mus[r * KDIM + k];
    const float inv2 = 1.0f / (s * s);

    const int c  = k >> 6;
    const int kk = k & 63;
    g_B2[(size_t)c * (NREL * 64) + r * 64 + kk]       = __float2bfloat16(-0.5f * inv2); // w2 <-> x^2
    g_B2[(size_t)(c + 8) * (NREL * 64) + r * 64 + kk] = __float2bfloat16(mu * inv2);    // w1 <-> x

    float part = -0.5f * mu * mu * inv2 - logf(s) - 0.9189385332046727f;

    __shared__ float red[16];
    #pragma unroll
    for (int off = 16; off > 0; off >>= 1)
        part += __shfl_down_sync(0xffffffffu, part, off);
    if ((k & 31) == 0) red[k >> 5] = part;
    __syncthreads();
    if (k < 16) {
        float v = red[k];
        #pragma unroll
        for (int off = 8; off > 0; off >>= 1)
            v += __shfl_down_sync(0x0000ffffu, v, off);
        if (k == 0) g_const[r] = v + priors[r] * (float)KDIM;
    }
}

// ---------------- main ----------------
// smem: A chunk-tiles [16][32*128B] = 64 KB, then B stages [NS][128*128B] = 64 KB
#define SMA_OFF(c) ((c) * 4096)
#define SMB_OFF(s) (16 * 4096 + (s) * 16384)
#define SMEM_TOTAL (16 * 4096 + NS * 16384)   // 131072

__global__ __launch_bounds__(512)
void nb_mma(const float* __restrict__ sbjs,
            const float* __restrict__ objs,
            float* __restrict__ out) {
    extern __shared__ char smem[];
    const uint32_t sb = smem_u32(smem);

    const int tid  = threadIdx.x;
    const int lane = tid & 31;
    const int wid  = tid >> 5;              // 0..15
    const int brow = blockIdx.x * MT;

    // ---- B loader mapping: 16 KB / 512 thr = 32 B each ----
    const int brw = tid >> 2;               // relation row 0..127
    const int bq  = tid & 3;                // 32-byte quarter of the 128B row
    uint32_t bStsOff[2];
    #pragma unroll
    for (int j = 0; j < 2; j++)
        bStsOff[j] = (uint32_t)(brw * 128 + ((bq * 32 + j * 16) ^ ((brw & 7) << 4)));

    auto issueB = [&](int c) {
        const char* src = reinterpret_cast<const char*>(g_B2) + (size_t)c * 16384 + tid * 32;
        const uint32_t dst = sb + SMB_OFF(c % NS);
        CP_ASYNC16(dst + bStsOff[0], src);
        CP_ASYNC16(dst + bStsOff[1], src + 16);
    };

    // ---- A preload: whole 32 x 1024 bf16 tile (x^2 chunks 0-7, x chunks 8-15) ----
    {
        const int asrc = tid & 1;                 // 0: sbjs, 1: objs
        const int arow = (tid >> 1) & 31;         // 0..31
        const int aseg = tid >> 6;                // 0..7 -> 32 floats at k = aseg*32
        const float* src = (asrc ? objs : sbjs) + (size_t)(brow + arow) * EMB + aseg * 32;
        const int c0   = (asrc * 8 + aseg) >> 1;  // chunk index for x^2 version
        const int koff = (aseg & 1) * 32;         // float offset within chunk
        char* dsq = smem + SMA_OFF(c0);
        char* drw = smem + SMA_OFF(c0 + 8);
        const uint32_t xr = (uint32_t)((arow & 7) << 4);
        #pragma unroll
        for (int j = 0; j < 8; j++) {
            const float4 v = reinterpret_cast<const float4*>(src)[j];
            __nv_bfloat162 r0 = __floats2bfloat162_rn(v.x, v.y);
            __nv_bfloat162 r1 = __floats2bfloat162_rn(v.z, v.w);
            __nv_bfloat162 q0 = __floats2bfloat162_rn(v.x * v.x, v.y * v.y);
            __nv_bfloat162 q1 = __floats2bfloat162_rn(v.z * v.z, v.w * v.w);
            const uint32_t bo = (uint32_t)(arow * 128 + (koff + j * 4) * 2);
            const uint32_t so = (bo & ~15u) | (((bo ^ xr) & 0x70u)) | (bo & 15u);
            // simpler: XOR only touches bits 4..6
            const uint32_t off = bo ^ xr;
            uint2 uq, ur;
            uq.x = *reinterpret_cast<uint32_t*>(&q0);
            uq.y = *reinterpret_cast<uint32_t*>(&q1);
            ur.x = *reinterpret_cast<uint32_t*>(&r0);
            ur.y = *reinterpret_cast<uint32_t*>(&r1);
            *reinterpret_cast<uint2*>(dsq + off) = uq;
            *reinterpret_cast<uint2*>(drw + off) = ur;
            (void)so;
        }
    }

    // ---- B prologue: chunks 0..2 ----
    #pragma unroll
    for (int p = 0; p < NS - 1; p++) { issueB(p); CP_COMMIT(); }

    // ---- compute mappings: warp tile 16(m) x 16(n) ----
    const int wm = wid & 1;                 // m offset 16
    const int wn = wid >> 1;                // n offset 16 (0..7)
    const int mrow = wm * 16 + (lane & 15);
    const uint32_t aLdRow = (uint32_t)(mrow * 128);
    const uint32_t aLdXor = (uint32_t)((mrow & 7) << 4);
    const uint32_t aLdBlk = (uint32_t)((lane >> 4) * 16);

    const int nrow = wn * 16 + ((lane >> 4) * 8) + (lane & 7);
    const uint32_t bLdBlk = (uint32_t)(((lane >> 3) & 1) * 16);
    const uint32_t bLdRow = (uint32_t)(nrow * 128);
    const uint32_t bLdXor = (uint32_t)((nrow & 7) << 4);

    float acc[2][4];
    #pragma unroll
    for (int i = 0; i < 2; i++)
        #pragma unroll
        for (int j = 0; j < 4; j++) acc[i][j] = 0.0f;

    __syncthreads();   // A resident + stage-0 spacing

    // ---- main loop ----
    for (int c = 0; c < NCHUNK; c++) {
        CP_WAIT2();
        __syncthreads();
        if (c + NS - 1 < NCHUNK) issueB(c + NS - 1);
        CP_COMMIT();

        const uint32_t aB = sb + SMA_OFF(c);
        const uint32_t bB = sb + SMB_OFF(c % NS);
        #pragma unroll
        for (int ks = 0; ks < 4; ks++) {
            const uint32_t kcol = (uint32_t)(ks * 32);
            uint32_t a[4];
            ldsm_x4(a[0], a[1], a[2], a[3], aB + aLdRow + ((kcol + aLdBlk) ^ aLdXor));
            uint32_t b[4];
            ldsm_x4(b[0], b[1], b[2], b[3], bB + bLdRow + ((kcol + bLdBlk) ^ bLdXor));
            mma16816(acc[0], a, b[0], b[1]);
            mma16816(acc[1], a, b[2], b[3]);
        }
        __syncthreads();   // all warps done with stage before its cp.async overwrite
    }

    // ---- epilogue: accum + const -> global ----
    #pragma unroll
    for (int nf = 0; nf < 2; nf++) {
        const int n0 = wn * 16 + nf * 8 + (lane & 3) * 2;
        const float c0 = g_const[n0], c1 = g_const[n0 + 1];
        const int r0 = brow + wm * 16 + (lane >> 2);
        float2 o0, o1;
        o0.x = acc[nf][0] + c0; o0.y = acc[nf][1] + c1;
        o1.x = acc[nf][2] + c0; o1.y = acc[nf][3] + c1;
        *reinterpret_cast<float2*>(&out[(size_t)r0 * NREL + n0])       = o0;
        *reinterpret_cast<float2*>(&out[(size_t)(r0 + 8) * NREL + n0]) = o1;
    }
}

extern "C" void kernel_launch(void* const* d_in, const int* in_sizes, int n_in,
                              void* d_out, int out_size) {
    const float* sbjs   = (const float*)d_in[0];
    const float* objs   = (const float*)d_in[1];
    const float* mus    = (const float*)d_in[2];
    const float* sigmas = (const float*)d_in[3];
    const float* priors = (const float*)d_in[4];
    float* out = (float*)d_out;

    cudaFuncSetAttribute(nb_mma, cudaFuncAttributeMaxDynamicSharedMemorySize, SMEM_TOTAL);

    prep_kernel<<<NREL, KDIM>>>(mus, sigmas, priors);
    nb_mma<<<BATCH / MT, 512, SMEM_TOTAL>>>(sbjs, objs, out);
    (void)in_sizes; (void)n_in; (void)out_size;
}

// round 6
// speedup vs baseline: 1.4483x; 1.1530x over previous
#include <cuda_runtime.h>
#include <cuda_bf16.h>
#include <cstdint>

#define BATCH  4096
#define NREL   128
#define EMB    256
#define KDIM   512
#define NITER  8          // 16 K-chunks of 64, two per iteration
#define NS     3          // pipeline stages (32 KB each)

// ---------------- device globals ----------------
// A pre-packed: [64 mtiles][16 chunks][64 rows x 128B, swizzled]  (8 MB)
__device__ __align__(128) __nv_bfloat16 g_A[BATCH * 1024];
// B pre-packed: [2 ntiles][16 chunks][64 rows x 128B, swizzled]   (256 KB)
__device__ __align__(128) __nv_bfloat16 g_Bs[NREL * 1024];
__device__ __align__(16) float g_const[NREL];

// ---------------- helpers ----------------
__device__ __forceinline__ uint32_t smem_u32(const void* p) {
    uint32_t a;
    asm("{ .reg .u64 t; cvta.to.shared.u64 t, %1; cvt.u32.u64 %0, t; }" : "=r"(a) : "l"(p));
    return a;
}
__device__ __forceinline__ void ldsm_x4(uint32_t& r0, uint32_t& r1, uint32_t& r2, uint32_t& r3,
                                        uint32_t addr) {
    asm volatile("ldmatrix.sync.aligned.m8n8.x4.shared.b16 {%0,%1,%2,%3}, [%4];"
                 : "=r"(r0), "=r"(r1), "=r"(r2), "=r"(r3) : "r"(addr));
}
__device__ __forceinline__ void mma16816(float* d, const uint32_t* a, uint32_t b0, uint32_t b1) {
    asm volatile(
        "mma.sync.aligned.m16n8k16.row.col.f32.bf16.bf16.f32 "
        "{%0,%1,%2,%3}, {%4,%5,%6,%7}, {%8,%9}, {%0,%1,%2,%3};"
        : "+f"(d[0]), "+f"(d[1]), "+f"(d[2]), "+f"(d[3])
        : "r"(a[0]), "r"(a[1]), "r"(a[2]), "r"(a[3]), "r"(b0), "r"(b1));
}
#define MBAR_INIT(addr, cnt) \
    asm volatile("mbarrier.init.shared.b64 [%0], %1;" :: "r"(addr), "r"((uint32_t)(cnt)) : "memory")
#define MBAR_EXPECT_TX(addr, bytes) \
    asm volatile("mbarrier.arrive.expect_tx.shared.b64 _, [%0], %1;" :: "r"(addr), "r"((uint32_t)(bytes)) : "memory")
#define MBAR_WAIT(addr, par) do { \
    uint32_t _m = (addr); uint32_t _p = (par); uint32_t _d; \
    asm volatile("{\n\t.reg .pred p;\n\tmbarrier.try_wait.parity.acquire.cta.shared::cta.b64 p, [%1], %2;\n\tselp.b32 %0, 1, 0, p;\n\t}" \
        : "=r"(_d) : "r"(_m), "r"(_p) : "memory"); \
    if (!_d) { \
        asm volatile("{\n\t.reg .pred P1;\n\tWL_%=: \n\tmbarrier.try_wait.parity.acquire.cta.shared::cta.b64 P1, [%0], %1, 0x989680;\n\t@P1 bra.uni WD_%=;\n\tbra.uni WL_%=;\n\tWD_%=: \n\t}" \
            :: "r"(_m), "r"(_p) : "memory"); \
    } } while (0)
#define CP_BULK(dst, src, sz, mbar) \
    asm volatile("cp.async.bulk.shared::cta.global.mbarrier::complete_tx::bytes [%0], [%1], %2, [%3];" \
        :: "r"(dst), "l"(src), "r"((uint32_t)(sz)), "r"(mbar) : "memory")

#define SWZ(bo) ((bo) ^ (((bo) >> 3) & 0x70))

// ---------------- merged prep: pack A (blocks 0..1023) and B (1024..1151) ----------------
__global__ void prep_all(const float* __restrict__ sbjs,
                         const float* __restrict__ objs,
                         const float* __restrict__ mus,
                         const float* __restrict__ sigmas,
                         const float* __restrict__ priors) {
    if (blockIdx.x < 1024) {
        // ---- A: each thread packs 8 k-values of one batch row ----
        const int g   = blockIdx.x * 256 + threadIdx.x;
        const int row = g >> 6;            // 0..4095
        const int k   = (g & 63) * 8;      // 0..504
        const float* src = (k < EMB) ? sbjs + (size_t)row * EMB + k
                                     : objs + (size_t)row * EMB + (k - EMB);
        const float4 v0 = reinterpret_cast<const float4*>(src)[0];
        const float4 v1 = reinterpret_cast<const float4*>(src)[1];

        __nv_bfloat162 r0 = __floats2bfloat162_rn(v0.x, v0.y);
        __nv_bfloat162 r1 = __floats2bfloat162_rn(v0.z, v0.w);
        __nv_bfloat162 r2 = __floats2bfloat162_rn(v1.x, v1.y);
        __nv_bfloat162 r3 = __floats2bfloat162_rn(v1.z, v1.w);
        __nv_bfloat162 q0 = __floats2bfloat162_rn(v0.x * v0.x, v0.y * v0.y);
        __nv_bfloat162 q1 = __floats2bfloat162_rn(v0.z * v0.z, v0.w * v0.w);
        __nv_bfloat162 q2 = __floats2bfloat162_rn(v1.x * v1.x, v1.y * v1.y);
        __nv_bfloat162 q3 = __floats2bfloat162_rn(v1.z * v1.z, v1.w * v1.w);
        uint4 ur, uq;
        ur.x = *reinterpret_cast<uint32_t*>(&r0); ur.y = *reinterpret_cast<uint32_t*>(&r1);
        ur.z = *reinterpret_cast<uint32_t*>(&r2); ur.w = *reinterpret_cast<uint32_t*>(&r3);
        uq.x = *reinterpret_cast<uint32_t*>(&q0); uq.y = *reinterpret_cast<uint32_t*>(&q1);
        uq.z = *reinterpret_cast<uint32_t*>(&q2); uq.w = *reinterpret_cast<uint32_t*>(&q3);

        const int mt  = row >> 6;          // mtile 0..63
        const int rin = row & 63;
        const int c   = k >> 6;            // chunk 0..7
        const uint32_t off = SWZ((uint32_t)(rin * 128 + (k & 63) * 2));
        char* base = reinterpret_cast<char*>(g_A);
        *reinterpret_cast<uint4*>(base + ((size_t)mt * 16 + c)     * 8192 + off) = uq; // x^2
        *reinterpret_cast<uint4*>(base + ((size_t)mt * 16 + c + 8) * 8192 + off) = ur; // x
    } else {
        // ---- B + const: one block per relation, 256 threads x 2 k ----
        const int r = blockIdx.x - 1024;   // 0..127
        const int t = threadIdx.x;
        const int nt  = r >> 6;            // ntile
        const int rin = r & 63;
        char* base = reinterpret_cast<char*>(g_Bs);

        float part = 0.0f;
        #pragma unroll
        for (int i = 0; i < 2; i++) {
            const int k = t + i * 256;     // 0..511
            const float s    = sigmas[r * KDIM + k];
            const float mu   = mus[r * KDIM + k];
            const float inv2 = 1.0f / (s * s);
            const int c  = k >> 6;
            const uint32_t off = SWZ((uint32_t)(rin * 128 + (k & 63) * 2));
            *reinterpret_cast<__nv_bfloat16*>(base + ((size_t)nt * 16 + c)     * 8192 + off)
                = __float2bfloat16(-0.5f * inv2);        // w2 <-> x^2
            *reinterpret_cast<__nv_bfloat16*>(base + ((size_t)nt * 16 + c + 8) * 8192 + off)
                = __float2bfloat16(mu * inv2);           // w1 <-> x
            part += -0.5f * mu * mu * inv2 - logf(s) - 0.9189385332046727f;
        }

        __shared__ float red[8];
        #pragma unroll
        for (int off = 16; off > 0; off >>= 1)
            part += __shfl_down_sync(0xffffffffu, part, off);
        if ((t & 31) == 0) red[t >> 5] = part;
        __syncthreads();
        if (t < 8) {
            float v = red[t];
            #pragma unroll
            for (int off = 4; off > 0; off >>= 1)
                v += __shfl_down_sync(0x000000ffu, v, off);
            if (t == 0) g_const[r] = v + priors[r] * (float)KDIM;
        }
    }
}

// ---------------- main: bulk-copy pipelined bf16 HMMA GEMM ----------------
// stage = [A chunk0 8K][A chunk1 8K][B chunk0 8K][B chunk1 8K] = 32 KB
#define STAGE_BYTES 32768
#define MBAR_OFF    (NS * STAGE_BYTES)
#define SMEM_TOTAL  (NS * STAGE_BYTES + 64)

__global__ __launch_bounds__(512)
void nb_mma(float* __restrict__ out) {
    extern __shared__ char smem[];
    const uint32_t sb = smem_u32(smem);

    const int tid  = threadIdx.x;
    const int lane = tid & 31;
    const int wid  = tid >> 5;              // 0..15
    const int mtile = blockIdx.x >> 1;      // 0..63
    const int ntile = blockIdx.x & 1;       // 0..1

    if (tid == 0) {
        #pragma unroll
        for (int s = 0; s < NS; s++) MBAR_INIT(sb + MBAR_OFF + s * 8, 1);
    }
    __syncthreads();

    const char* aSrc = reinterpret_cast<const char*>(g_A)  + (size_t)mtile * 16 * 8192;
    const char* bSrc = reinterpret_cast<const char*>(g_Bs) + (size_t)ntile * 16 * 8192;

    auto issue = [&](int it, int s) {
        const uint32_t mb  = sb + MBAR_OFF + s * 8;
        const uint32_t dst = sb + s * STAGE_BYTES;
        MBAR_EXPECT_TX(mb, STAGE_BYTES);
        CP_BULK(dst,         aSrc + (size_t)(2 * it)     * 8192, 8192, mb);
        CP_BULK(dst + 8192,  aSrc + (size_t)(2 * it + 1) * 8192, 8192, mb);
        CP_BULK(dst + 16384, bSrc + (size_t)(2 * it)     * 8192, 8192, mb);
        CP_BULK(dst + 24576, bSrc + (size_t)(2 * it + 1) * 8192, 8192, mb);
    };

    if (tid == 0) { issue(0, 0); issue(1, 1); }

    // ---- compute mappings: warp tile 16(m) x 16(n), CTA tile 64x64 ----
    const int wm = wid & 3;
    const int wn = wid >> 2;
    const int mrow = wm * 16 + (lane & 15);
    const uint32_t aLdRow = (uint32_t)(mrow * 128);
    const uint32_t aLdXor = (uint32_t)((mrow & 7) << 4);
    const uint32_t aLdBlk = (uint32_t)((lane >> 4) * 16);

    const int nrow = wn * 16 + ((lane >> 4) * 8) + (lane & 7);
    const uint32_t bLdRow = (uint32_t)(nrow * 128);
    const uint32_t bLdXor = (uint32_t)((nrow & 7) << 4);
    const uint32_t bLdBlk = (uint32_t)(((lane >> 3) & 1) * 16);

    float acc[2][4];
    #pragma unroll
    for (int i = 0; i < 2; i++)
        #pragma unroll
        for (int j = 0; j < 4; j++) acc[i][j] = 0.0f;

    for (int it = 0; it < NITER; it++) {
        const int s = it % NS;
        MBAR_WAIT(sb + MBAR_OFF + s * 8, (it / NS) & 1);
        __syncthreads();                        // all warps past stage (it-1)
        if (tid == 0 && it + 2 < NITER) issue(it + 2, (it + 2) % NS);

        const uint32_t stage = sb + s * STAGE_BYTES;
        #pragma unroll
        for (int kc = 0; kc < 2; kc++) {
            const uint32_t aB = stage + kc * 8192;
            const uint32_t bB = stage + 16384 + kc * 8192;
            #pragma unroll
            for (int ks = 0; ks < 4; ks++) {
                const uint32_t kcol = (uint32_t)(ks * 32);
                uint32_t a[4];
                ldsm_x4(a[0], a[1], a[2], a[3], aB + aLdRow + ((kcol + aLdBlk) ^ aLdXor));
                uint32_t b[4];
                ldsm_x4(b[0], b[1], b[2], b[3], bB + bLdRow + ((kcol + bLdBlk) ^ bLdXor));
                mma16816(acc[0], a, b[0], b[1]);
                mma16816(acc[1], a, b[2], b[3]);
            }
        }
    }

    // ---- epilogue ----
    #pragma unroll
    for (int nf = 0; nf < 2; nf++) {
        const int n0 = ntile * 64 + wn * 16 + nf * 8 + (lane & 3) * 2;
        const float c0 = g_const[n0], c1 = g_const[n0 + 1];
        const int r0 = mtile * 64 + wm * 16 + (lane >> 2);
        float2 o0, o1;
        o0.x = acc[nf][0] + c0; o0.y = acc[nf][1] + c1;
        o1.x = acc[nf][2] + c0; o1.y = acc[nf][3] + c1;
        *reinterpret_cast<float2*>(&out[(size_t)r0 * NREL + n0])       = o0;
        *reinterpret_cast<float2*>(&out[(size_t)(r0 + 8) * NREL + n0]) = o1;
    }
}

extern "C" void kernel_launch(void* const* d_in, const int* in_sizes, int n_in,
                              void* d_out, int out_size) {
    const float* sbjs   = (const float*)d_in[0];
    const float* objs   = (const float*)d_in[1];
    const float* mus    = (const float*)d_in[2];
    const float* sigmas = (const float*)d_in[3];
    const float* priors = (const float*)d_in[4];
    float* out = (float*)d_out;

    cudaFuncSetAttribute(nb_mma, cudaFuncAttributeMaxDynamicSharedMemorySize, SMEM_TOTAL);

    prep_all<<<1152, 256>>>(sbjs, objs, mus, sigmas, priors);
    nb_mma<<<128, 512, SMEM_TOTAL>>>(out);
    (void)in_sizes; (void)n_in; (void)out_size;
}